// round 10
// baseline (speedup 1.0000x reference)
#include <cuda_runtime.h>
#include <cuda_bf16.h>

#define NH  4096
#define DIN 4096

// Warp-autonomous GEMV: one 32-thread block per (dot, j) pair.
//   dot0: Wih[j]      . x    dot1: Whh[j]      . h   (i gate)
//   dot2: Wih[nh+j]   . x    dot3: Whh[nh+j]   . h   (f gate)
//   dot4: Wih[2nh+j]  . x    dot5: Whh[2nh+j]  . h   (g gate; x-dot reused by o gate,
//   dot6: Whh[3nh+j]  . h                             reference sets Wio = Wig slice)
// No __syncthreads, no block coupling: each warp retires independently, the
// 7th-arriving warp per j finalizes the activations inline (counter pattern).
// Grid 28672 x 32thr -> 32 blocks/SM, waves = 6.05 (tail ~1%).

__device__ float        g_partial[NH * 8];   // [j*8 + dot], padded to 32B per j
__device__ unsigned int g_count  [NH];       // zero-init; finalizer resets to 0

__global__ __launch_bounds__(32)
void lstm_dot_kernel(const float* __restrict__ x,
                     const float* __restrict__ h,
                     const float* __restrict__ c,
                     const float* __restrict__ Wih,
                     const float* __restrict__ Whh,
                     const float* __restrict__ bih,
                     const float* __restrict__ bhh,
                     float* __restrict__ out)
{
    const int bid  = blockIdx.x;
    const int dot  = bid >> 12;          // 0..6  (contiguous j-range per dot region)
    const int j    = bid & (NH - 1);
    const int lane = threadIdx.x;

    // Branchless per-dot selection. use_h: 0 -> (Wih, x), 1 -> (Whh, h).
    const int use_h_tab[7] = {0, 1, 0, 1, 0, 1, 1};
    const int gate_tab [7] = {0, 0, 1, 1, 2, 2, 3};
    const int use_h = use_h_tab[dot];
    const int gate  = gate_tab[dot];

    const float* W = use_h ? Whh : Wih;
    const float* v = use_h ? h   : x;
    const long  row = (long)gate * NH + j;

    const float4* __restrict__ Wr = reinterpret_cast<const float4*>(W + row * (long)DIN);
    const float4* __restrict__ vr = reinterpret_cast<const float4*>(v);

    // 1024 float4 per row / 32 lanes = 32 float4 per lane.
    // 4 independent accumulators + batched loads -> MLP for DRAM latency hiding.
    float a0 = 0.f, a1 = 0.f, a2 = 0.f, a3 = 0.f;
    #pragma unroll
    for (int it = 0; it < 8; ++it) {
        const int base = it * 128 + lane;
        float4 w0 = Wr[base];        float4 x0 = vr[base];
        float4 w1 = Wr[base + 32];   float4 x1 = vr[base + 32];
        float4 w2 = Wr[base + 64];   float4 x2 = vr[base + 64];
        float4 w3 = Wr[base + 96];   float4 x3 = vr[base + 96];
        a0 += w0.x*x0.x + w0.y*x0.y + w0.z*x0.z + w0.w*x0.w;
        a1 += w1.x*x1.x + w1.y*x1.y + w1.z*x1.z + w1.w*x1.w;
        a2 += w2.x*x2.x + w2.y*x2.y + w2.z*x2.z + w2.w*x2.w;
        a3 += w3.x*x3.x + w3.y*x3.y + w3.z*x3.z + w3.w*x3.w;
    }
    float acc = (a0 + a1) + (a2 + a3);

    // Warp tree-reduce.
    #pragma unroll
    for (int off = 16; off > 0; off >>= 1)
        acc += __shfl_down_sync(0xffffffffu, acc, off);

    if (lane == 0) {
        g_partial[j * 8 + dot] = acc;
        __threadfence();                              // partial visible before count bump
        const unsigned old = atomicAdd(&g_count[j], 1u);
        if (old == 6u) {                              // 7th arrival: finalize this j
            __threadfence();                          // order loads after observing count
            const float d0 = __ldcg(&g_partial[j * 8 + 0]);  // i . x
            const float d1 = __ldcg(&g_partial[j * 8 + 1]);  // i . h
            const float d2 = __ldcg(&g_partial[j * 8 + 2]);  // f . x
            const float d3 = __ldcg(&g_partial[j * 8 + 3]);  // f . h
            const float d4 = __ldcg(&g_partial[j * 8 + 4]);  // g . x  (also o . x)
            const float d5 = __ldcg(&g_partial[j * 8 + 5]);  // g . h
            const float d6 = __ldcg(&g_partial[j * 8 + 6]);  // o . h

            const float ai = d0 + d1 + __ldg(&bih[j])        + __ldg(&bhh[j]);
            const float af = d2 + d3 + __ldg(&bih[NH + j])   + __ldg(&bhh[NH + j]);
            const float ag = d4 + d5 + __ldg(&bih[2*NH + j]) + __ldg(&bhh[2*NH + j]);
            const float ao = d4 + d6 + __ldg(&bih[3*NH + j]) + __ldg(&bhh[3*NH + j]);

            const float it_ = 1.f / (1.f + __expf(-ai));
            const float ft_ = 1.f / (1.f + __expf(-af));
            const float gt_ = tanhf(ag);
            const float ot_ = 1.f / (1.f + __expf(-ao));
            const float ct_ = ft_ * __ldg(&c[j]) + it_ * gt_;
            const float ht_ = ot_ * tanhf(ct_);

            out[j         ] = it_;
            out[NH   + j  ] = ft_;
            out[2*NH + j  ] = gt_;
            out[3*NH + j  ] = ot_;
            out[4*NH + j  ] = ct_;
            out[5*NH + j  ] = ht_;

            g_count[j] = 0u;   // reset for next graph replay (kernel boundary publishes)
        }
    }
}

extern "C" void kernel_launch(void* const* d_in, const int* in_sizes, int n_in,
                              void* d_out, int out_size)
{
    const float* x   = (const float*)d_in[0];
    const float* h   = (const float*)d_in[1];
    const float* c   = (const float*)d_in[2];
    const float* Wih = (const float*)d_in[3];
    const float* Whh = (const float*)d_in[4];
    const float* bih = (const float*)d_in[5];
    const float* bhh = (const float*)d_in[6];
    float* out = (float*)d_out;

    lstm_dot_kernel<<<7 * NH, 32>>>(x, h, c, Wih, Whh, bih, bhh, out);
}

// round 11
// speedup vs baseline: 1.0466x; 1.0466x over previous
#include <cuda_runtime.h>
#include <cuda_bf16.h>

#define NH  4096
#define DIN 4096

// One block per output index j. 7 warps = 7 full-row dot products (16KB streams):
//   w0: Wih[j]      . x     w1: Whh[j]      . h      (i gate)
//   w2: Wih[nh+j]   . x     w3: Whh[nh+j]   . h      (f gate)
//   w4: Wih[2nh+j]  . x     w5: Whh[2nh+j]  . h      (g gate)
//   w6: Whh[3nh+j]  . h                              (o gate; x-part REUSES w4,
//                                                     reference sets Wio = Wig slice)
// Weights are read-once: __ldcs (evict-first) keeps them from thrashing L2,
// so x/h (32KB, reused by every warp on the chip) stay L2-resident.
__global__ __launch_bounds__(224)
void lstm_cell_kernel(const float* __restrict__ x,
                      const float* __restrict__ h,
                      const float* __restrict__ c,
                      const float* __restrict__ Wih,
                      const float* __restrict__ Whh,
                      const float* __restrict__ bih,
                      const float* __restrict__ bhh,
                      float* __restrict__ out)
{
    const int j    = blockIdx.x;
    const int wid  = threadIdx.x >> 5;
    const int lane = threadIdx.x & 31;

    __shared__ float partial[7];

    // Branchless per-warp dot-product selection.
    // use_h[w]: 0 -> (Wih, x), 1 -> (Whh, h).  gate[w]: row block multiplier.
    const int use_h_tab[7] = {0, 1, 0, 1, 0, 1, 1};
    const int gate_tab [7] = {0, 0, 1, 1, 2, 2, 3};
    const int use_h = use_h_tab[wid];
    const int gate  = gate_tab[wid];

    const float* W = use_h ? Whh : Wih;
    const float* v = use_h ? h   : x;
    const long  row = (long)gate * NH + j;

    const float4* __restrict__ Wr = reinterpret_cast<const float4*>(W + row * (long)DIN);
    const float4* __restrict__ vr = reinterpret_cast<const float4*>(v);

    // 1024 float4 per row / 32 lanes = 32 float4 per lane.
    // 4 independent accumulators + batched loads -> MLP for DRAM latency hiding.
    float a0 = 0.f, a1 = 0.f, a2 = 0.f, a3 = 0.f;
    #pragma unroll
    for (int it = 0; it < 8; ++it) {
        const int base = it * 128 + lane;           // stride 32 between the 4 loads below
        float4 w0 = __ldcs(&Wr[base]);        float4 x0 = vr[base];
        float4 w1 = __ldcs(&Wr[base + 32]);   float4 x1 = vr[base + 32];
        float4 w2 = __ldcs(&Wr[base + 64]);   float4 x2 = vr[base + 64];
        float4 w3 = __ldcs(&Wr[base + 96]);   float4 x3 = vr[base + 96];
        a0 += w0.x*x0.x + w0.y*x0.y + w0.z*x0.z + w0.w*x0.w;
        a1 += w1.x*x1.x + w1.y*x1.y + w1.z*x1.z + w1.w*x1.w;
        a2 += w2.x*x2.x + w2.y*x2.y + w2.z*x2.z + w2.w*x2.w;
        a3 += w3.x*x3.x + w3.y*x3.y + w3.z*x3.z + w3.w*x3.w;
    }
    float acc = (a0 + a1) + (a2 + a3);

    // Warp tree-reduce.
    #pragma unroll
    for (int off = 16; off > 0; off >>= 1)
        acc += __shfl_down_sync(0xffffffffu, acc, off);

    if (lane == 0) partial[wid] = acc;
    __syncthreads();

    if (threadIdx.x == 0) {
        const float ai = partial[0] + partial[1] + __ldg(&bih[j])        + __ldg(&bhh[j]);
        const float af = partial[2] + partial[3] + __ldg(&bih[NH + j])   + __ldg(&bhh[NH + j]);
        const float ag = partial[4] + partial[5] + __ldg(&bih[2*NH + j]) + __ldg(&bhh[2*NH + j]);
        // o gate: x-part = g gate's x-dot (reference's Wio slice aliases Wig)
        const float ao = partial[4] + partial[6] + __ldg(&bih[3*NH + j]) + __ldg(&bhh[3*NH + j]);

        const float it_ = 1.f / (1.f + __expf(-ai));
        const float ft_ = 1.f / (1.f + __expf(-af));
        const float gt_ = tanhf(ag);
        const float ot_ = 1.f / (1.f + __expf(-ao));
        const float ct_ = ft_ * __ldg(&c[j]) + it_ * gt_;
        const float ht_ = ot_ * tanhf(ct_);

        out[j         ] = it_;
        out[NH   + j  ] = ft_;
        out[2*NH + j  ] = gt_;
        out[3*NH + j  ] = ot_;
        out[4*NH + j  ] = ct_;
        out[5*NH + j  ] = ht_;
    }
}

extern "C" void kernel_launch(void* const* d_in, const int* in_sizes, int n_in,
                              void* d_out, int out_size)
{
    const float* x   = (const float*)d_in[0];
    const float* h   = (const float*)d_in[1];
    const float* c   = (const float*)d_in[2];
    const float* Wih = (const float*)d_in[3];
    const float* Whh = (const float*)d_in[4];
    const float* bih = (const float*)d_in[5];
    const float* bhh = (const float*)d_in[6];
    float* out = (float*)d_out;

    lstm_cell_kernel<<<NH, 224>>>(x, h, c, Wih, Whh, bih, bhh, out);
}